// round 13
// baseline (speedup 1.0000x reference)
#include <cuda_runtime.h>
#include <cuda_bf16.h>

// Problem constants
#define B     16
#define N1P   1024
#define N2P   4096
#define N1    (B * N1P)      // 16384 queries
#define N2    (B * N2P)      // 65536 sources
#define D_IN  64
#define H1    128
#define H2    256
#define KNB   32
#define R2    0.04f

#define MT    2              // m-tiles per query (32 nbr rows)
#define KS    16             // k-steps (128 / 8)
#define QPC   2              // queries per conv CTA
#define CMT   4              // m-tiles per conv CTA

typedef unsigned int uint;

// ---------------- scratch (static device globals; no allocations) ----------
__device__ float g_y2[(size_t)N2 * H1];     // x2 @ W1[:64] + b1  (33.5 MB)
__device__ int   g_nbr[(size_t)N1 * KNB];
__device__ int   g_cnt[N1];
__device__ uint  g_bh[KS * 8 * 32 * 8];     // W2 tf32 fragments (128 KB)
__device__ float g_self[(size_t)N1 * H2];   // self-row @ W2, raw (16 MB)

// ---------------- tf32 helpers ---------------------------------------------
__device__ __forceinline__ uint tf32r(float f) {
    uint u; asm("cvt.rna.tf32.f32 %0, %1;" : "=r"(u) : "f"(f)); return u;
}
__device__ __forceinline__ void mma_tf32(float* c, uint a0, uint a1, uint a2,
                                         uint a3, uint b0, uint b1) {
    asm("mma.sync.aligned.m16n8k8.row.col.f32.tf32.tf32.f32 "
        "{%0,%1,%2,%3},{%4,%5,%6,%7},{%8,%9},{%0,%1,%2,%3};"
        : "+f"(c[0]), "+f"(c[1]), "+f"(c[2]), "+f"(c[3])
        : "r"(a0), "r"(a1), "r"(a2), "r"(a3), "r"(b0), "r"(b1));
}

// ================ kernel 1: y2 = x2 @ W1[0:64] + b1 ========================
// 2-row interleave: two independent FMA chains per thread to hide fma latency.
#define PR_ROWS 64
__global__ __launch_bounds__(128) void precompute_y2_kernel(
    const float* __restrict__ x2, const float* __restrict__ W1,
    const float* __restrict__ b1)
{
    __shared__ __align__(16) float xs[PR_ROWS * D_IN];
    int c = threadIdx.x;
    float w[D_IN];
    #pragma unroll
    for (int d = 0; d < D_IN; ++d) w[d] = W1[d * H1 + c];
    float bc = b1[c];

    size_t rbase = (size_t)blockIdx.x * PR_ROWS;
    const float4* src  = (const float4*)(x2 + rbase * D_IN);
    float4*       dst4 = (float4*)xs;
    for (int i = c; i < PR_ROWS * D_IN / 4; i += 128) dst4[i] = src[i];
    __syncthreads();

    for (int r = 0; r < PR_ROWS; r += 2) {
        const float4* xr0 = (const float4*)(xs + r * D_IN);
        const float4* xr1 = (const float4*)(xs + (r + 1) * D_IN);
        float a0 = bc, a1 = bc;
        #pragma unroll
        for (int t = 0; t < D_IN / 4; ++t) {
            float4 v0 = xr0[t];
            float4 v1 = xr1[t];
            a0 = fmaf(v0.x, w[4 * t],     a0);  a1 = fmaf(v1.x, w[4 * t],     a1);
            a0 = fmaf(v0.y, w[4 * t + 1], a0);  a1 = fmaf(v1.y, w[4 * t + 1], a1);
            a0 = fmaf(v0.z, w[4 * t + 2], a0);  a1 = fmaf(v1.z, w[4 * t + 2], a1);
            a0 = fmaf(v0.w, w[4 * t + 3], a0);  a1 = fmaf(v1.w, w[4 * t + 3], a1);
        }
        g_y2[(rbase + r) * H1 + c]     = a0;
        g_y2[(rbase + r + 1) * H1 + c] = a1;
    }
}

// ================ kernel 1b: W2 -> tf32 fragment layout ====================
// idx i -> [((ks*8+G)*32 + t)*8 + w]; w = NT*2+word;  (G: 32-col group 0..7)
// source element: W2[8*ks + (t%4) + 4*word][G*32 + NT*8 + t/4]
__global__ __launch_bounds__(256) void bfrag_kernel(const float* __restrict__ W2)
{
    int i = blockIdx.x * 256 + threadIdx.x;         // 32768 total
    int w    = i & 7;
    int t    = (i >> 3) & 31;
    int g    = (i >> 8) & 7;
    int ks   = i >> 11;
    int nt   = w >> 1;
    int word = w & 1;
    int k = 8 * ks + (t & 3) + 4 * word;
    int n = g * 32 + nt * 8 + (t >> 2);
    g_bh[i] = tf32r(W2[k * H2 + n]);
}

// ================ kernel 2: ball query (warp per query) ====================
__global__ void ball_query_kernel(const float* __restrict__ pos1,
                                  const float* __restrict__ pos2)
{
    int gw   = (blockIdx.x * blockDim.x + threadIdx.x) >> 5;
    int lane = threadIdx.x & 31;
    if (gw >= N1) return;
    int q = gw;
    float qx = pos1[3 * q], qy = pos1[3 * q + 1], qz = pos1[3 * q + 2];
    float qn = qx * qx + qy * qy + qz * qz;
    int base = (q >> 10) << 12;
    int cnt = 0;
    for (int chunk = 0; chunk < N2P / 32; ++chunk) {
        int s = base + chunk * 32 + lane;
        float sx = pos2[3 * s], sy = pos2[3 * s + 1], sz = pos2[3 * s + 2];
        float sn  = sx * sx + sy * sy + sz * sz;
        float dot = qx * sx + qy * sy + qz * sz;
        float sq  = qn + sn - 2.0f * dot;
        bool inb = (sq <= R2);
        unsigned m = __ballot_sync(0xffffffffu, inb);
        if (inb) {
            int slot = cnt + __popc(m & ((1u << lane) - 1u));
            if (slot < KNB) g_nbr[(size_t)q * KNB + slot] = s;
        }
        cnt += __popc(m);
        if (cnt >= KNB) break;
    }
    if (lane == 0) g_cnt[q] = (cnt < KNB) ? cnt : KNB;
}

// ================ kernel 2b: dense self-row GEMM ===========================
// g_self[q][:] = m1_self[q] @ W2  (raw, no bias/relu).
__global__ __launch_bounds__(256) void self_gemm_kernel(
    const float* __restrict__ pos1, const float* __restrict__ pos2,
    const float* __restrict__ W1)
{
    __shared__ __align__(16) uint afrag[4 * KS * 32 * 4];   // 32 KB
    __shared__ float dxs[64], dys[64], dzs[64];

    int tid   = threadIdx.x;
    int qbase = blockIdx.x * 64;

    if (tid < 64) {
        int q0 = qbase + tid;
        dxs[tid] = pos2[3 * q0]     - pos1[3 * q0];
        dys[tid] = pos2[3 * q0 + 1] - pos1[3 * q0 + 1];
        dzs[tid] = pos2[3 * q0 + 2] - pos1[3 * q0 + 2];
    }
    __syncthreads();

    {
        int c  = tid & 127;
        int rh = tid >> 7;              // 0,1 -> rows rh*32 .. rh*32+31
        float wx = W1[64 * H1 + c], wy = W1[65 * H1 + c], wz = W1[66 * H1 + c];
        int ks = c >> 3;
        #pragma unroll
        for (int r = 0; r < 32; ++r) {
            int n = rh * 32 + r;
            float t = g_y2[(size_t)(qbase + n) * H1 + c];
            t = fmaf(dxs[n], wx, t);
            t = fmaf(dys[n], wy, t);
            t = fmaf(dzs[n], wz, t);
            float v = fmaxf(t, 0.0f);
            int mt = n >> 4;
            int rl = n & 15;
            int tt = ((rl & 7) << 2) | (c & 3);
            int w  = (rl >> 3) | (((c >> 2) & 1) << 1);
            afrag[((mt * KS + ks) * 32 + tt) * 4 + w] = tf32r(v);
        }
    }
    __syncthreads();

    int g = tid >> 5;
    int t = tid & 31;

    float acc[4][4][4];
    #pragma unroll
    for (int mt = 0; mt < 4; ++mt)
        #pragma unroll
        for (int nt = 0; nt < 4; ++nt)
            #pragma unroll
            for (int i = 0; i < 4; ++i) acc[mt][nt][i] = 0.0f;

    for (int ks = 0; ks < KS; ++ks) {
        uint4 a[4];
        #pragma unroll
        for (int mt = 0; mt < 4; ++mt)
            a[mt] = *(const uint4*)&afrag[((mt * KS + ks) * 32 + t) * 4];
        size_t bofs = ((size_t)(ks * 8 + g) * 32 + t) * 8;
        uint4 b01 = *(const uint4*)&g_bh[bofs];
        uint4 b23 = *(const uint4*)&g_bh[bofs + 4];
        #pragma unroll
        for (int mt = 0; mt < 4; ++mt) {
            mma_tf32(acc[mt][0], a[mt].x, a[mt].y, a[mt].z, a[mt].w, b01.x, b01.y);
            mma_tf32(acc[mt][1], a[mt].x, a[mt].y, a[mt].z, a[mt].w, b01.z, b01.w);
            mma_tf32(acc[mt][2], a[mt].x, a[mt].y, a[mt].z, a[mt].w, b23.x, b23.y);
            mma_tf32(acc[mt][3], a[mt].x, a[mt].y, a[mt].z, a[mt].w, b23.z, b23.w);
        }
    }

    #pragma unroll
    for (int mt = 0; mt < 4; ++mt) {
        int r0 = qbase + mt * 16 + (t >> 2);
        #pragma unroll
        for (int nt = 0; nt < 4; ++nt) {
            int col = g * 32 + nt * 8 + (t & 3) * 2;
            g_self[(size_t)r0 * H2 + col]           = acc[mt][nt][0];
            g_self[(size_t)r0 * H2 + col + 1]       = acc[mt][nt][1];
            g_self[(size_t)(r0 + 8) * H2 + col]     = acc[mt][nt][2];
            g_self[(size_t)(r0 + 8) * H2 + col + 1] = acc[mt][nt][3];
        }
    }
}

// ================ kernel 3: neighbor MLP, 2 queries / CTA, 64 cols / warp ==
// 256 threads, 8 warps. Warp g: query qi=g>>2 (m-tiles 2*qi..2*qi+1),
// cols [ (g&3)*64, (g&3)*64+64 ) = 8 n-tiles. Per ks: 2 A-LDS + 4 B-LDG,
// 16 mma -> 8 mma per LDS (2x R12), A-smem reads halved per query.
__global__ __launch_bounds__(256, 2) void conv_kernel(
    const float* __restrict__ pos1, const float* __restrict__ pos2,
    const float* __restrict__ W1,   const float* __restrict__ b2,
    float* __restrict__ out)
{
    __shared__ __align__(16) uint afrag[CMT * KS * 32 * 4];  // 32 KB
    __shared__ int   jb[QPC * KNB];
    __shared__ float dxs[QPC * KNB], dys[QPC * KNB], dzs[QPC * KNB];

    int qbase = blockIdx.x * QPC;
    int tid   = threadIdx.x;

    if (tid < QPC * KNB) {
        int n  = tid;
        int qq = qbase + (n >> 5);
        int l  = n & 31;
        int cq = g_cnt[qq];
        int j  = (l < cq) ? g_nbr[(size_t)qq * KNB + l] : qq;  // pad -> self
        jb[n] = j;
        dxs[n] = pos2[3 * j]     - pos1[3 * qq];
        dys[n] = pos2[3 * j + 1] - pos1[3 * qq + 1];
        dzs[n] = pos2[3 * j + 2] - pos1[3 * qq + 2];
    }
    __syncthreads();

    // ---- pass 1: 64 rows, split in 2 halves; col = tid % 128 ----
    {
        int c  = tid & 127;
        int rh = tid >> 7;                  // 0,1 -> rows rh*32 .. rh*32+31
        float wx = W1[64 * H1 + c], wy = W1[65 * H1 + c], wz = W1[66 * H1 + c];
        int ks = c >> 3;
        #pragma unroll
        for (int r = 0; r < 32; ++r) {
            int n = rh * 32 + r;
            float t = g_y2[(size_t)jb[n] * H1 + c];
            t = fmaf(dxs[n], wx, t);
            t = fmaf(dys[n], wy, t);
            t = fmaf(dzs[n], wz, t);
            float v = fmaxf(t, 0.0f);
            int mt = n >> 4;
            int rl = n & 15;
            int tt = ((rl & 7) << 2) | (c & 3);
            int w  = (rl >> 3) | (((c >> 2) & 1) << 1);
            afrag[((mt * KS + ks) * 32 + tt) * 4 + w] = tf32r(v);
        }
    }
    __syncthreads();

    // ---- pass 2: 16 mma per k-step per warp ----
    int g  = tid >> 5;
    int t  = tid & 31;
    int qi = g >> 2;           // which query this warp serves
    int ng = g & 3;            // 64-col group

    float acc[MT][8][4];
    #pragma unroll
    for (int mt = 0; mt < MT; ++mt)
        #pragma unroll
        for (int nt = 0; nt < 8; ++nt)
            #pragma unroll
            for (int i = 0; i < 4; ++i) acc[mt][nt][i] = 0.0f;

    #pragma unroll 2
    for (int ks = 0; ks < KS; ++ks) {
        uint4 a[MT];
        #pragma unroll
        for (int mt = 0; mt < MT; ++mt)
            a[mt] = *(const uint4*)&afrag[(((2 * qi + mt) * KS + ks) * 32 + t) * 4];
        size_t b0 = ((size_t)(ks * 8 + 2 * ng) * 32 + t) * 8;        // group 2ng
        size_t b1 = ((size_t)(ks * 8 + 2 * ng + 1) * 32 + t) * 8;    // group 2ng+1
        uint4 w01 = *(const uint4*)&g_bh[b0];
        uint4 w23 = *(const uint4*)&g_bh[b0 + 4];
        uint4 w45 = *(const uint4*)&g_bh[b1];
        uint4 w67 = *(const uint4*)&g_bh[b1 + 4];
        #pragma unroll
        for (int mt = 0; mt < MT; ++mt) {
            mma_tf32(acc[mt][0], a[mt].x, a[mt].y, a[mt].z, a[mt].w, w01.x, w01.y);
            mma_tf32(acc[mt][1], a[mt].x, a[mt].y, a[mt].z, a[mt].w, w01.z, w01.w);
            mma_tf32(acc[mt][2], a[mt].x, a[mt].y, a[mt].z, a[mt].w, w23.x, w23.y);
            mma_tf32(acc[mt][3], a[mt].x, a[mt].y, a[mt].z, a[mt].w, w23.z, w23.w);
            mma_tf32(acc[mt][4], a[mt].x, a[mt].y, a[mt].z, a[mt].w, w45.x, w45.y);
            mma_tf32(acc[mt][5], a[mt].x, a[mt].y, a[mt].z, a[mt].w, w45.z, w45.w);
            mma_tf32(acc[mt][6], a[mt].x, a[mt].y, a[mt].z, a[mt].w, w67.x, w67.y);
            mma_tf32(acc[mt][7], a[mt].x, a[mt].y, a[mt].z, a[mt].w, w67.z, w67.w);
        }
    }

    // ---- epilogue: max over nbr rows + self (g_self), bias, relu ----
    int qq = qbase + qi;
    #pragma unroll
    for (int nt = 0; nt < 8; ++nt) {
        float vA = fmaxf(acc[0][nt][0], acc[0][nt][2]);
        float vB = fmaxf(acc[0][nt][1], acc[0][nt][3]);
        vA = fmaxf(vA, fmaxf(acc[1][nt][0], acc[1][nt][2]));
        vB = fmaxf(vB, fmaxf(acc[1][nt][1], acc[1][nt][3]));
        #pragma unroll
        for (int o = 4; o < 32; o <<= 1) {
            vA = fmaxf(vA, __shfl_xor_sync(0xffffffffu, vA, o));
            vB = fmaxf(vB, __shfl_xor_sync(0xffffffffu, vB, o));
        }
        if (t < 4) {
            int colA = ng * 64 + nt * 8 + t * 2;
            vA = fmaxf(vA, g_self[(size_t)qq * H2 + colA]);
            vB = fmaxf(vB, g_self[(size_t)qq * H2 + colA + 1]);
            out[(size_t)qq * H2 + colA]     = fmaxf(vA + b2[colA], 0.0f);
            out[(size_t)qq * H2 + colA + 1] = fmaxf(vB + b2[colA + 1], 0.0f);
        }
    }
}

// =========================== launcher ======================================
extern "C" void kernel_launch(void* const* d_in, const int* in_sizes, int n_in,
                              void* d_out, int out_size)
{
    // inputs: 0:x1 1:pos1 2:batch1(i64) 3:x2 4:pos2 5:batch2(i64)
    //         6:W1[67,128] 7:b1[128] 8:W2[128,256] 9:b2[256]
    const float* pos1 = (const float*)d_in[1];
    const float* x2   = (const float*)d_in[3];
    const float* pos2 = (const float*)d_in[4];
    const float* W1   = (const float*)d_in[6];
    const float* b1   = (const float*)d_in[7];
    const float* W2   = (const float*)d_in[8];
    const float* b2   = (const float*)d_in[9];
    float* out = (float*)d_out;

    precompute_y2_kernel<<<N2 / PR_ROWS, 128>>>(x2, W1, b1);
    bfrag_kernel<<<KS * 8 * 32 * 8 / 256, 256>>>(W2);
    ball_query_kernel<<<(N1 * 32 + 255) / 256, 256>>>(pos1, pos2);
    self_gemm_kernel<<<N1 / 64, 256>>>(pos1, pos2, W1);
    conv_kernel<<<N1 / QPC, 256>>>(pos1, pos2, W1, b2, out);
}

// round 14
// speedup vs baseline: 1.2377x; 1.2377x over previous
#include <cuda_runtime.h>
#include <cuda_bf16.h>

// Problem constants
#define B     16
#define N1P   1024
#define N2P   4096
#define N1    (B * N1P)      // 16384 queries
#define N2    (B * N2P)      // 65536 sources
#define D_IN  64
#define H1    128
#define H2    256
#define KNB   32
#define R2    0.04f

#define MT    2              // m-tiles per query (32 nbr rows)
#define KS    16             // k-steps (128 / 8)
#define RS    132            // afrag row stride in uints (bank-conflict pad)

typedef unsigned int uint;

// ---------------- scratch (static device globals; no allocations) ----------
__device__ float g_y2[(size_t)N2 * H1];     // x2@W1[:64] + b1 + pos2.W1pos
__device__ float g_p1w[(size_t)N1 * H1];    // pos1 . W1[64:67]  (8 MB)
__device__ int   g_nbr[(size_t)N1 * KNB];
__device__ int   g_cnt[N1];
__device__ uint  g_bh[KS * 8 * 32 * 8];     // W2 tf32 fragments (128 KB)
__device__ float g_self[(size_t)N1 * H2];   // self-row @ W2, raw (16 MB)

// ---------------- tf32 helpers ---------------------------------------------
__device__ __forceinline__ uint tf32r(float f) {
    uint u; asm("cvt.rna.tf32.f32 %0, %1;" : "=r"(u) : "f"(f)); return u;
}
__device__ __forceinline__ void mma_tf32(float* c, uint a0, uint a1, uint a2,
                                         uint a3, uint b0, uint b1) {
    asm("mma.sync.aligned.m16n8k8.row.col.f32.tf32.tf32.f32 "
        "{%0,%1,%2,%3},{%4,%5,%6,%7},{%8,%9},{%0,%1,%2,%3};"
        : "+f"(c[0]), "+f"(c[1]), "+f"(c[2]), "+f"(c[3])
        : "r"(a0), "r"(a1), "r"(a2), "r"(a3), "r"(b0), "r"(b1));
}

// ================ kernel 1: y2p = x2 @ W1[0:64] + b1 + pos2 . W1pos ========
#define PR_ROWS 64
__global__ __launch_bounds__(128) void precompute_y2_kernel(
    const float* __restrict__ x2, const float* __restrict__ pos2,
    const float* __restrict__ W1, const float* __restrict__ b1)
{
    __shared__ __align__(16) float xs[PR_ROWS * D_IN];
    __shared__ float ps[PR_ROWS * 3];
    int c = threadIdx.x;
    float w[D_IN];
    #pragma unroll
    for (int d = 0; d < D_IN; ++d) w[d] = W1[d * H1 + c];
    float wpx = W1[64 * H1 + c], wpy = W1[65 * H1 + c], wpz = W1[66 * H1 + c];
    float bc = b1[c];

    size_t rbase = (size_t)blockIdx.x * PR_ROWS;
    const float4* src  = (const float4*)(x2 + rbase * D_IN);
    float4*       dst4 = (float4*)xs;
    for (int i = c; i < PR_ROWS * D_IN / 4; i += 128) dst4[i] = src[i];
    for (int i = c; i < PR_ROWS * 3; i += 128) ps[i] = pos2[rbase * 3 + i];
    __syncthreads();

    for (int r = 0; r < PR_ROWS; r += 2) {
        const float4* xr0 = (const float4*)(xs + r * D_IN);
        const float4* xr1 = (const float4*)(xs + (r + 1) * D_IN);
        float a0 = bc, a1 = bc;
        a0 = fmaf(ps[3 * r],     wpx, a0);  a1 = fmaf(ps[3 * r + 3], wpx, a1);
        a0 = fmaf(ps[3 * r + 1], wpy, a0);  a1 = fmaf(ps[3 * r + 4], wpy, a1);
        a0 = fmaf(ps[3 * r + 2], wpz, a0);  a1 = fmaf(ps[3 * r + 5], wpz, a1);
        #pragma unroll
        for (int t = 0; t < D_IN / 4; ++t) {
            float4 v0 = xr0[t];
            float4 v1 = xr1[t];
            a0 = fmaf(v0.x, w[4 * t],     a0);  a1 = fmaf(v1.x, w[4 * t],     a1);
            a0 = fmaf(v0.y, w[4 * t + 1], a0);  a1 = fmaf(v1.y, w[4 * t + 1], a1);
            a0 = fmaf(v0.z, w[4 * t + 2], a0);  a1 = fmaf(v1.z, w[4 * t + 2], a1);
            a0 = fmaf(v0.w, w[4 * t + 3], a0);  a1 = fmaf(v1.w, w[4 * t + 3], a1);
        }
        g_y2[(rbase + r) * H1 + c]     = a0;
        g_y2[(rbase + r + 1) * H1 + c] = a1;
    }
}

// ================ kernel 1c: p1w[q][c] = pos1[q] . W1[64:67, c] ============
__global__ __launch_bounds__(256) void p1w_kernel(
    const float* __restrict__ pos1, const float* __restrict__ W1)
{
    int idx = blockIdx.x * 256 + threadIdx.x;   // N1*H1 = 2M total
    int q = idx >> 7;
    int c = idx & 127;
    float v = pos1[3 * q] * W1[64 * H1 + c];
    v = fmaf(pos1[3 * q + 1], W1[65 * H1 + c], v);
    v = fmaf(pos1[3 * q + 2], W1[66 * H1 + c], v);
    g_p1w[idx] = v;
}

// ================ kernel 1b: W2 -> tf32 fragment layout ====================
__global__ __launch_bounds__(256) void bfrag_kernel(const float* __restrict__ W2)
{
    int i = blockIdx.x * 256 + threadIdx.x;         // 32768 total
    int w    = i & 7;
    int t    = (i >> 3) & 31;
    int g    = (i >> 8) & 7;
    int ks   = i >> 11;
    int nt   = w >> 1;
    int word = w & 1;
    int k = 8 * ks + (t & 3) + 4 * word;
    int n = g * 32 + nt * 8 + (t >> 2);
    g_bh[i] = tf32r(W2[k * H2 + n]);
}

// ================ kernel 2: ball query (warp per query) ====================
__global__ void ball_query_kernel(const float* __restrict__ pos1,
                                  const float* __restrict__ pos2)
{
    int gw   = (blockIdx.x * blockDim.x + threadIdx.x) >> 5;
    int lane = threadIdx.x & 31;
    if (gw >= N1) return;
    int q = gw;
    float qx = pos1[3 * q], qy = pos1[3 * q + 1], qz = pos1[3 * q + 2];
    float qn = qx * qx + qy * qy + qz * qz;
    int base = (q >> 10) << 12;
    int cnt = 0;
    for (int chunk = 0; chunk < N2P / 32; ++chunk) {
        int s = base + chunk * 32 + lane;
        float sx = pos2[3 * s], sy = pos2[3 * s + 1], sz = pos2[3 * s + 2];
        float sn  = sx * sx + sy * sy + sz * sz;
        float dot = qx * sx + qy * sy + qz * sz;
        float sq  = qn + sn - 2.0f * dot;
        bool inb = (sq <= R2);
        unsigned m = __ballot_sync(0xffffffffu, inb);
        if (inb) {
            int slot = cnt + __popc(m & ((1u << lane) - 1u));
            if (slot < KNB) g_nbr[(size_t)q * KNB + slot] = s;
        }
        cnt += __popc(m);
        if (cnt >= KNB) break;
    }
    if (lane == 0) g_cnt[q] = (cnt < KNB) ? cnt : KNB;
}

// ================ kernel 2b: dense self-row GEMM ===========================
// g_self[q][:] = relu(y2p[q] - p1w[q]) @ W2  (raw, no bias/relu on output).
__global__ __launch_bounds__(256) void self_gemm_kernel()
{
    __shared__ __align__(16) uint afrag[4 * KS * 32 * 4];   // 32 KB
    int tid   = threadIdx.x;
    int qbase = blockIdx.x * 64;

    {
        int c  = tid & 127;
        int rh = tid >> 7;              // 0,1 -> rows rh*32 .. rh*32+31
        int ks = c >> 3;
        #pragma unroll
        for (int r = 0; r < 32; ++r) {
            int n = rh * 32 + r;
            size_t qi = (size_t)(qbase + n) * H1 + c;
            float v = fmaxf(g_y2[qi] - g_p1w[qi], 0.0f);
            int mt = n >> 4;
            int rl = n & 15;
            int tt = ((rl & 7) << 2) | (c & 3);
            int w  = (rl >> 3) | (((c >> 2) & 1) << 1);
            afrag[((mt * KS + ks) * 32 + tt) * 4 + w] = tf32r(v);
        }
    }
    __syncthreads();

    int g = tid >> 5;
    int t = tid & 31;

    float acc[4][4][4];
    #pragma unroll
    for (int mt = 0; mt < 4; ++mt)
        #pragma unroll
        for (int nt = 0; nt < 4; ++nt)
            #pragma unroll
            for (int i = 0; i < 4; ++i) acc[mt][nt][i] = 0.0f;

    for (int ks = 0; ks < KS; ++ks) {
        uint4 a[4];
        #pragma unroll
        for (int mt = 0; mt < 4; ++mt)
            a[mt] = *(const uint4*)&afrag[((mt * KS + ks) * 32 + t) * 4];
        size_t bofs = ((size_t)(ks * 8 + g) * 32 + t) * 8;
        uint4 b01 = *(const uint4*)&g_bh[bofs];
        uint4 b23 = *(const uint4*)&g_bh[bofs + 4];
        #pragma unroll
        for (int mt = 0; mt < 4; ++mt) {
            mma_tf32(acc[mt][0], a[mt].x, a[mt].y, a[mt].z, a[mt].w, b01.x, b01.y);
            mma_tf32(acc[mt][1], a[mt].x, a[mt].y, a[mt].z, a[mt].w, b01.z, b01.w);
            mma_tf32(acc[mt][2], a[mt].x, a[mt].y, a[mt].z, a[mt].w, b23.x, b23.y);
            mma_tf32(acc[mt][3], a[mt].x, a[mt].y, a[mt].z, a[mt].w, b23.z, b23.w);
        }
    }

    #pragma unroll
    for (int mt = 0; mt < 4; ++mt) {
        int r0 = qbase + mt * 16 + (t >> 2);
        #pragma unroll
        for (int nt = 0; nt < 4; ++nt) {
            int col = g * 32 + nt * 8 + (t & 3) * 2;
            g_self[(size_t)r0 * H2 + col]           = acc[mt][nt][0];
            g_self[(size_t)r0 * H2 + col + 1]       = acc[mt][nt][1];
            g_self[(size_t)(r0 + 8) * H2 + col]     = acc[mt][nt][2];
            g_self[(size_t)(r0 + 8) * H2 + col + 1] = acc[mt][nt][3];
        }
    }
}

// ================ kernel 3: per-query neighbor MLP via tf32 mma ============
// R12 shape: 256 thr / query, 8 warps x 32 cols, MT=2, 4 CTAs/SM.
// pass1 slimmed via y2p/p1w fold; afrag stride 132 halves STS conflicts;
// B prefetched; g_self loads hoisted over the shuffle reduction.
__global__ __launch_bounds__(256, 4) void conv_kernel(
    const float* __restrict__ b2, float* __restrict__ out)
{
    __shared__ __align__(16) uint afrag[MT * KS * RS];  // 16.9 KB
    __shared__ int jb[KNB];

    int q   = blockIdx.x;
    int tid = threadIdx.x;
    int cnt = g_cnt[q];

    if (tid < KNB) {
        int n = tid;
        jb[n] = (n < cnt) ? g_nbr[(size_t)q * KNB + n] : q;  // pad -> self
    }
    __syncthreads();

    // ---- pass 1: 32 rows, split in 2 halves; col = tid % 128 ----
    {
        int c  = tid & 127;
        int rh = tid >> 7;                  // 0,1 -> rows rh*16 .. rh*16+15
        int ks = c >> 3;
        float p1wqc = g_p1w[(size_t)q * H1 + c];
        #pragma unroll
        for (int r = 0; r < 16; ++r) {
            int n = rh * 16 + r;
            float v = fmaxf(g_y2[(size_t)jb[n] * H1 + c] - p1wqc, 0.0f);
            int mt = n >> 4;
            int rl = n & 15;
            int tt = ((rl & 7) << 2) | (c & 3);
            int w  = (rl >> 3) | (((c >> 2) & 1) << 1);
            afrag[(mt * KS + ks) * RS + tt * 4 + w] = tf32r(v);
        }
    }
    __syncthreads();

    // ---- pass 2: 8 mma per k-step per warp, B prefetched one step ahead ----
    int g = tid >> 5;
    int t = tid & 31;

    float acc[MT][4][4];
    #pragma unroll
    for (int mt = 0; mt < MT; ++mt)
        #pragma unroll
        for (int nt = 0; nt < 4; ++nt)
            #pragma unroll
            for (int i = 0; i < 4; ++i) acc[mt][nt][i] = 0.0f;

    size_t bbase = ((size_t)g * 32 + t) * 8;      // + ks*8*32*8 per step
    uint4 b01 = *(const uint4*)&g_bh[bbase];
    uint4 b23 = *(const uint4*)&g_bh[bbase + 4];

    #pragma unroll
    for (int ks = 0; ks < KS; ++ks) {
        uint4 a[MT];
        #pragma unroll
        for (int mt = 0; mt < MT; ++mt)
            a[mt] = *(const uint4*)&afrag[(mt * KS + ks) * RS + t * 4];
        uint4 nb01, nb23;
        if (ks + 1 < KS) {
            size_t nofs = bbase + (size_t)(ks + 1) * (8 * 32 * 8);
            nb01 = *(const uint4*)&g_bh[nofs];
            nb23 = *(const uint4*)&g_bh[nofs + 4];
        }
        #pragma unroll
        for (int mt = 0; mt < MT; ++mt) {
            mma_tf32(acc[mt][0], a[mt].x, a[mt].y, a[mt].z, a[mt].w, b01.x, b01.y);
            mma_tf32(acc[mt][1], a[mt].x, a[mt].y, a[mt].z, a[mt].w, b01.z, b01.w);
            mma_tf32(acc[mt][2], a[mt].x, a[mt].y, a[mt].z, a[mt].w, b23.x, b23.y);
            mma_tf32(acc[mt][3], a[mt].x, a[mt].y, a[mt].z, a[mt].w, b23.z, b23.w);
        }
        if (ks + 1 < KS) { b01 = nb01; b23 = nb23; }
    }

    // ---- epilogue: prefetch g_self, then max + bias + relu ----
    float sA[4], sB[4];
    if (t < 4) {
        #pragma unroll
        for (int nt = 0; nt < 4; ++nt) {
            int colA = g * 32 + nt * 8 + t * 2;
            sA[nt] = g_self[(size_t)q * H2 + colA];
            sB[nt] = g_self[(size_t)q * H2 + colA + 1];
        }
    }
    #pragma unroll
    for (int nt = 0; nt < 4; ++nt) {
        float vA = fmaxf(acc[0][nt][0], acc[0][nt][2]);
        float vB = fmaxf(acc[0][nt][1], acc[0][nt][3]);
        vA = fmaxf(vA, fmaxf(acc[1][nt][0], acc[1][nt][2]));
        vB = fmaxf(vB, fmaxf(acc[1][nt][1], acc[1][nt][3]));
        #pragma unroll
        for (int o = 4; o < 32; o <<= 1) {
            vA = fmaxf(vA, __shfl_xor_sync(0xffffffffu, vA, o));
            vB = fmaxf(vB, __shfl_xor_sync(0xffffffffu, vB, o));
        }
        if (t < 4) {
            int colA = g * 32 + nt * 8 + t * 2;
            vA = fmaxf(vA, sA[nt]);
            vB = fmaxf(vB, sB[nt]);
            out[(size_t)q * H2 + colA]     = fmaxf(vA + b2[colA], 0.0f);
            out[(size_t)q * H2 + colA + 1] = fmaxf(vB + b2[colA + 1], 0.0f);
        }
    }
}

// =========================== launcher ======================================
extern "C" void kernel_launch(void* const* d_in, const int* in_sizes, int n_in,
                              void* d_out, int out_size)
{
    // inputs: 0:x1 1:pos1 2:batch1(i64) 3:x2 4:pos2 5:batch2(i64)
    //         6:W1[67,128] 7:b1[128] 8:W2[128,256] 9:b2[256]
    const float* pos1 = (const float*)d_in[1];
    const float* x2   = (const float*)d_in[3];
    const float* pos2 = (const float*)d_in[4];
    const float* W1   = (const float*)d_in[6];
    const float* b1   = (const float*)d_in[7];
    const float* W2   = (const float*)d_in[8];
    const float* b2   = (const float*)d_in[9];
    float* out = (float*)d_out;

    precompute_y2_kernel<<<N2 / PR_ROWS, 128>>>(x2, pos2, W1, b1);
    p1w_kernel<<<N1 * H1 / 256, 256>>>(pos1, W1);
    bfrag_kernel<<<KS * 8 * 32 * 8 / 256, 256>>>(W2);
    ball_query_kernel<<<(N1 * 32 + 255) / 256, 256>>>(pos1, pos2);
    self_gemm_kernel<<<N1 / 64, 256>>>();
    conv_kernel<<<N1, 256>>>(b2, out);
}

// round 15
// speedup vs baseline: 1.3056x; 1.0548x over previous
#include <cuda_runtime.h>
#include <cuda_bf16.h>

// Problem constants
#define B     16
#define N1P   1024
#define N2P   4096
#define N1    (B * N1P)      // 16384 queries
#define N2    (B * N2P)      // 65536 sources
#define D_IN  64
#define H1    128
#define H2    256
#define KNB   32
#define R2    0.04f

#define MT    2              // m-tiles per query (32 nbr rows)
#define KS    16             // k-steps (128 / 8)
#define RS    132            // afrag row stride in uints (bank-conflict pad)

typedef unsigned int uint;

// ---------------- scratch (static device globals; no allocations) ----------
__device__ float g_y2[(size_t)N2 * H1];     // x2@W1[:64] + b1 + pos2.W1pos
__device__ float g_p1w[(size_t)N1 * H1];    // pos1 . W1[64:67]  (8 MB)
__device__ int   g_nbr[(size_t)N1 * KNB];
__device__ int   g_cnt[N1];
__device__ uint  g_bh[KS * 8 * 32 * 8];     // W2 tf32 fragments (128 KB)
__device__ float g_self[(size_t)N1 * H2];   // self-row @ W2, raw (16 MB)

// ---------------- tf32 helpers ---------------------------------------------
__device__ __forceinline__ uint tf32r(float f) {
    uint u; asm("cvt.rna.tf32.f32 %0, %1;" : "=r"(u) : "f"(f)); return u;
}
__device__ __forceinline__ void mma_tf32(float* c, uint a0, uint a1, uint a2,
                                         uint a3, uint b0, uint b1) {
    asm("mma.sync.aligned.m16n8k8.row.col.f32.tf32.tf32.f32 "
        "{%0,%1,%2,%3},{%4,%5,%6,%7},{%8,%9},{%0,%1,%2,%3};"
        : "+f"(c[0]), "+f"(c[1]), "+f"(c[2]), "+f"(c[3])
        : "r"(a0), "r"(a1), "r"(a2), "r"(a3), "r"(b0), "r"(b1));
}

// ================ kernel 1: y2p = x2 @ W1[0:64] + b1 + pos2 . W1pos ========
#define PR_ROWS 64
__global__ __launch_bounds__(128) void precompute_y2_kernel(
    const float* __restrict__ x2, const float* __restrict__ pos2,
    const float* __restrict__ W1, const float* __restrict__ b1)
{
    __shared__ __align__(16) float xs[PR_ROWS * D_IN];
    __shared__ float ps[PR_ROWS * 3];
    int c = threadIdx.x;
    float w[D_IN];
    #pragma unroll
    for (int d = 0; d < D_IN; ++d) w[d] = W1[d * H1 + c];
    float wpx = W1[64 * H1 + c], wpy = W1[65 * H1 + c], wpz = W1[66 * H1 + c];
    float bc = b1[c];

    size_t rbase = (size_t)blockIdx.x * PR_ROWS;
    const float4* src  = (const float4*)(x2 + rbase * D_IN);
    float4*       dst4 = (float4*)xs;
    for (int i = c; i < PR_ROWS * D_IN / 4; i += 128) dst4[i] = src[i];
    for (int i = c; i < PR_ROWS * 3; i += 128) ps[i] = pos2[rbase * 3 + i];
    __syncthreads();

    for (int r = 0; r < PR_ROWS; r += 2) {
        const float4* xr0 = (const float4*)(xs + r * D_IN);
        const float4* xr1 = (const float4*)(xs + (r + 1) * D_IN);
        float a0 = bc, a1 = bc;
        a0 = fmaf(ps[3 * r],     wpx, a0);  a1 = fmaf(ps[3 * r + 3], wpx, a1);
        a0 = fmaf(ps[3 * r + 1], wpy, a0);  a1 = fmaf(ps[3 * r + 4], wpy, a1);
        a0 = fmaf(ps[3 * r + 2], wpz, a0);  a1 = fmaf(ps[3 * r + 5], wpz, a1);
        #pragma unroll
        for (int t = 0; t < D_IN / 4; ++t) {
            float4 v0 = xr0[t];
            float4 v1 = xr1[t];
            a0 = fmaf(v0.x, w[4 * t],     a0);  a1 = fmaf(v1.x, w[4 * t],     a1);
            a0 = fmaf(v0.y, w[4 * t + 1], a0);  a1 = fmaf(v1.y, w[4 * t + 1], a1);
            a0 = fmaf(v0.z, w[4 * t + 2], a0);  a1 = fmaf(v1.z, w[4 * t + 2], a1);
            a0 = fmaf(v0.w, w[4 * t + 3], a0);  a1 = fmaf(v1.w, w[4 * t + 3], a1);
        }
        g_y2[(rbase + r) * H1 + c]     = a0;
        g_y2[(rbase + r + 1) * H1 + c] = a1;
    }
}

// ================ kernel 1c: p1w[q][c] = pos1[q] . W1[64:67, c] ============
__global__ __launch_bounds__(256) void p1w_kernel(
    const float* __restrict__ pos1, const float* __restrict__ W1)
{
    int idx = blockIdx.x * 256 + threadIdx.x;   // N1*H1 = 2M total
    int q = idx >> 7;
    int c = idx & 127;
    float v = pos1[3 * q] * W1[64 * H1 + c];
    v = fmaf(pos1[3 * q + 1], W1[65 * H1 + c], v);
    v = fmaf(pos1[3 * q + 2], W1[66 * H1 + c], v);
    g_p1w[idx] = v;
}

// ================ kernel 1b: W2 -> tf32 fragment layout ====================
__global__ __launch_bounds__(256) void bfrag_kernel(const float* __restrict__ W2)
{
    int i = blockIdx.x * 256 + threadIdx.x;         // 32768 total
    int w    = i & 7;
    int t    = (i >> 3) & 31;
    int g    = (i >> 8) & 7;
    int ks   = i >> 11;
    int nt   = w >> 1;
    int word = w & 1;
    int k = 8 * ks + (t & 3) + 4 * word;
    int n = g * 32 + nt * 8 + (t >> 2);
    g_bh[i] = tf32r(W2[k * H2 + n]);
}

// ================ kernel 2: ball query (warp per query) ====================
// Group-of-4-chunk unroll: 12 loads + 4 ballots issue without intervening
// branches; early-exit check once per 128 sources. Slot assignment stays
// exact (monotone cnt + ballot prefix, guarded by slot < KNB).
__global__ void ball_query_kernel(const float* __restrict__ pos1,
                                  const float* __restrict__ pos2)
{
    int gw   = (blockIdx.x * blockDim.x + threadIdx.x) >> 5;
    int lane = threadIdx.x & 31;
    if (gw >= N1) return;
    int q = gw;
    float qx = pos1[3 * q], qy = pos1[3 * q + 1], qz = pos1[3 * q + 2];
    float qn = qx * qx + qy * qy + qz * qz;
    int base = (q >> 10) << 12;
    int cnt = 0;
    for (int grp = 0; grp < N2P / 128; ++grp) {
        int s0 = base + grp * 128 + lane;
        bool inb[4];
        #pragma unroll
        for (int u = 0; u < 4; ++u) {
            int s = s0 + u * 32;
            float sx = pos2[3 * s], sy = pos2[3 * s + 1], sz = pos2[3 * s + 2];
            float sn  = sx * sx + sy * sy + sz * sz;
            float dot = qx * sx + qy * sy + qz * sz;
            inb[u] = (qn + sn - 2.0f * dot <= R2);
        }
        #pragma unroll
        for (int u = 0; u < 4; ++u) {
            unsigned m = __ballot_sync(0xffffffffu, inb[u]);
            if (inb[u]) {
                int slot = cnt + __popc(m & ((1u << lane) - 1u));
                if (slot < KNB) g_nbr[(size_t)q * KNB + slot] = s0 + u * 32;
            }
            cnt += __popc(m);
        }
        if (cnt >= KNB) break;     // uniform across warp
    }
    if (lane == 0) g_cnt[q] = (cnt < KNB) ? cnt : KNB;
}

// ================ kernel 2b: dense self-row GEMM ===========================
// g_self[q][:] = relu(y2p[q] - p1w[q]) @ W2  (raw, no bias/relu on output).
__global__ __launch_bounds__(256) void self_gemm_kernel()
{
    __shared__ __align__(16) uint afrag[4 * KS * 32 * 4];   // 32 KB
    int tid   = threadIdx.x;
    int qbase = blockIdx.x * 64;

    {
        int c  = tid & 127;
        int rh = tid >> 7;              // 0,1 -> rows rh*32 .. rh*32+31
        int ks = c >> 3;
        #pragma unroll
        for (int r = 0; r < 32; ++r) {
            int n = rh * 32 + r;
            size_t qi = (size_t)(qbase + n) * H1 + c;
            float v = fmaxf(g_y2[qi] - g_p1w[qi], 0.0f);
            int mt = n >> 4;
            int rl = n & 15;
            int tt = ((rl & 7) << 2) | (c & 3);
            int w  = (rl >> 3) | (((c >> 2) & 1) << 1);
            afrag[((mt * KS + ks) * 32 + tt) * 4 + w] = tf32r(v);
        }
    }
    __syncthreads();

    int g = tid >> 5;
    int t = tid & 31;

    float acc[4][4][4];
    #pragma unroll
    for (int mt = 0; mt < 4; ++mt)
        #pragma unroll
        for (int nt = 0; nt < 4; ++nt)
            #pragma unroll
            for (int i = 0; i < 4; ++i) acc[mt][nt][i] = 0.0f;

    for (int ks = 0; ks < KS; ++ks) {
        uint4 a[4];
        #pragma unroll
        for (int mt = 0; mt < 4; ++mt)
            a[mt] = *(const uint4*)&afrag[((mt * KS + ks) * 32 + t) * 4];
        size_t bofs = ((size_t)(ks * 8 + g) * 32 + t) * 8;
        uint4 b01 = *(const uint4*)&g_bh[bofs];
        uint4 b23 = *(const uint4*)&g_bh[bofs + 4];
        #pragma unroll
        for (int mt = 0; mt < 4; ++mt) {
            mma_tf32(acc[mt][0], a[mt].x, a[mt].y, a[mt].z, a[mt].w, b01.x, b01.y);
            mma_tf32(acc[mt][1], a[mt].x, a[mt].y, a[mt].z, a[mt].w, b01.z, b01.w);
            mma_tf32(acc[mt][2], a[mt].x, a[mt].y, a[mt].z, a[mt].w, b23.x, b23.y);
            mma_tf32(acc[mt][3], a[mt].x, a[mt].y, a[mt].z, a[mt].w, b23.z, b23.w);
        }
    }

    #pragma unroll
    for (int mt = 0; mt < 4; ++mt) {
        int r0 = qbase + mt * 16 + (t >> 2);
        #pragma unroll
        for (int nt = 0; nt < 4; ++nt) {
            int col = g * 32 + nt * 8 + (t & 3) * 2;
            g_self[(size_t)r0 * H2 + col]           = acc[mt][nt][0];
            g_self[(size_t)r0 * H2 + col + 1]       = acc[mt][nt][1];
            g_self[(size_t)(r0 + 8) * H2 + col]     = acc[mt][nt][2];
            g_self[(size_t)(r0 + 8) * H2 + col + 1] = acc[mt][nt][3];
        }
    }
}

// ================ kernel 3: per-query neighbor MLP via tf32 mma ============
// 256 thr / query, 8 warps x 32 cols, MT=2, 4 CTAs/SM. y2p/p1w-folded pass1,
// stride-132 afrag, B prefetch, g_self epilogue hoist.
__global__ __launch_bounds__(256, 4) void conv_kernel(
    const float* __restrict__ b2, float* __restrict__ out)
{
    __shared__ __align__(16) uint afrag[MT * KS * RS];  // 16.9 KB
    __shared__ int jb[KNB];

    int q   = blockIdx.x;
    int tid = threadIdx.x;
    int cnt = g_cnt[q];

    if (tid < KNB) {
        int n = tid;
        jb[n] = (n < cnt) ? g_nbr[(size_t)q * KNB + n] : q;  // pad -> self
    }
    __syncthreads();

    // ---- pass 1: 32 rows, split in 2 halves; col = tid % 128 ----
    {
        int c  = tid & 127;
        int rh = tid >> 7;                  // 0,1 -> rows rh*16 .. rh*16+15
        int ks = c >> 3;
        float p1wqc = g_p1w[(size_t)q * H1 + c];
        #pragma unroll
        for (int r = 0; r < 16; ++r) {
            int n = rh * 16 + r;
            float v = fmaxf(g_y2[(size_t)jb[n] * H1 + c] - p1wqc, 0.0f);
            int mt = n >> 4;
            int rl = n & 15;
            int tt = ((rl & 7) << 2) | (c & 3);
            int w  = (rl >> 3) | (((c >> 2) & 1) << 1);
            afrag[(mt * KS + ks) * RS + tt * 4 + w] = tf32r(v);
        }
    }
    __syncthreads();

    // ---- pass 2: 8 mma per k-step per warp, B prefetched one step ahead ----
    int g = tid >> 5;
    int t = tid & 31;

    float acc[MT][4][4];
    #pragma unroll
    for (int mt = 0; mt < MT; ++mt)
        #pragma unroll
        for (int nt = 0; nt < 4; ++nt)
            #pragma unroll
            for (int i = 0; i < 4; ++i) acc[mt][nt][i] = 0.0f;

    size_t bbase = ((size_t)g * 32 + t) * 8;      // + ks*8*32*8 per step
    uint4 b01 = *(const uint4*)&g_bh[bbase];
    uint4 b23 = *(const uint4*)&g_bh[bbase + 4];

    #pragma unroll
    for (int ks = 0; ks < KS; ++ks) {
        uint4 a[MT];
        #pragma unroll
        for (int mt = 0; mt < MT; ++mt)
            a[mt] = *(const uint4*)&afrag[(mt * KS + ks) * RS + t * 4];
        uint4 nb01, nb23;
        if (ks + 1 < KS) {
            size_t nofs = bbase + (size_t)(ks + 1) * (8 * 32 * 8);
            nb01 = *(const uint4*)&g_bh[nofs];
            nb23 = *(const uint4*)&g_bh[nofs + 4];
        }
        #pragma unroll
        for (int mt = 0; mt < MT; ++mt) {
            mma_tf32(acc[mt][0], a[mt].x, a[mt].y, a[mt].z, a[mt].w, b01.x, b01.y);
            mma_tf32(acc[mt][1], a[mt].x, a[mt].y, a[mt].z, a[mt].w, b01.z, b01.w);
            mma_tf32(acc[mt][2], a[mt].x, a[mt].y, a[mt].z, a[mt].w, b23.x, b23.y);
            mma_tf32(acc[mt][3], a[mt].x, a[mt].y, a[mt].z, a[mt].w, b23.z, b23.w);
        }
        if (ks + 1 < KS) { b01 = nb01; b23 = nb23; }
    }

    // ---- epilogue: prefetch g_self, then max + bias + relu ----
    float sA[4], sB[4];
    if (t < 4) {
        #pragma unroll
        for (int nt = 0; nt < 4; ++nt) {
            int colA = g * 32 + nt * 8 + t * 2;
            sA[nt] = g_self[(size_t)q * H2 + colA];
            sB[nt] = g_self[(size_t)q * H2 + colA + 1];
        }
    }
    #pragma unroll
    for (int nt = 0; nt < 4; ++nt) {
        float vA = fmaxf(acc[0][nt][0], acc[0][nt][2]);
        float vB = fmaxf(acc[0][nt][1], acc[0][nt][3]);
        vA = fmaxf(vA, fmaxf(acc[1][nt][0], acc[1][nt][2]));
        vB = fmaxf(vB, fmaxf(acc[1][nt][1], acc[1][nt][3]));
        #pragma unroll
        for (int o = 4; o < 32; o <<= 1) {
            vA = fmaxf(vA, __shfl_xor_sync(0xffffffffu, vA, o));
            vB = fmaxf(vB, __shfl_xor_sync(0xffffffffu, vB, o));
        }
        if (t < 4) {
            int colA = g * 32 + nt * 8 + t * 2;
            vA = fmaxf(vA, sA[nt]);
            vB = fmaxf(vB, sB[nt]);
            out[(size_t)q * H2 + colA]     = fmaxf(vA + b2[colA], 0.0f);
            out[(size_t)q * H2 + colA + 1] = fmaxf(vB + b2[colA + 1], 0.0f);
        }
    }
}

// =========================== launcher ======================================
extern "C" void kernel_launch(void* const* d_in, const int* in_sizes, int n_in,
                              void* d_out, int out_size)
{
    // inputs: 0:x1 1:pos1 2:batch1(i64) 3:x2 4:pos2 5:batch2(i64)
    //         6:W1[67,128] 7:b1[128] 8:W2[128,256] 9:b2[256]
    const float* pos1 = (const float*)d_in[1];
    const float* x2   = (const float*)d_in[3];
    const float* pos2 = (const float*)d_in[4];
    const float* W1   = (const float*)d_in[6];
    const float* b1   = (const float*)d_in[7];
    const float* W2   = (const float*)d_in[8];
    const float* b2   = (const float*)d_in[9];
    float* out = (float*)d_out;

    precompute_y2_kernel<<<N2 / PR_ROWS, 128>>>(x2, pos2, W1, b1);
    p1w_kernel<<<N1 * H1 / 256, 256>>>(pos1, W1);
    bfrag_kernel<<<KS * 8 * 32 * 8 / 256, 256>>>(W2);
    ball_query_kernel<<<(N1 * 32 + 255) / 256, 256>>>(pos1, pos2);
    self_gemm_kernel<<<N1 / 64, 256>>>();
    conv_kernel<<<N1, 256>>>(b2, out);
}